// round 14
// baseline (speedup 1.0000x reference)
#include <cuda_runtime.h>

// ---------------------------------------------------------------------------
// R14: R11 body (best measured: 2 rows/warp, 256-thr blocks, integer ladder,
// epilogue short-circuit) + L2 evict_last on the gather path, via the
// cache-policy operand form (scalar ld with inline .L2::evict_last is
// rejected by ptxas on sm_103a; createpolicy + ld...L2::cache_hint is the
// supported encoding).
//
// Hypothesis (from R12 floor decomposition, still untested): DRAM traffic ==
// gather sectors (~1.1MB) on every graph replay although the same 8192 lines
// are re-read each replay and fit easily in 126MB L2. Pinning them with an
// evict_last policy should convert steady-state gathers from DRAM (~577+cyc)
// to L2 hits (~234cyc), shrinking the exposed addr->gather chain.
//
// Reference semantics (verified R2-R12, rel_err 3.279e-6):
//  * value = |mem[b, addr[b]]| exactly (eq_gate is an exact one-hot).
//  * floor(v/10^p) == unsigned /10 ladder on u = (unsigned)v  (v < 2^24).
//  * n = 1 + #{p in 1..5 : q_p != 0}.
//  * qmax clipping per pos {999,101,11,2,1,1} (reference loop break).
//  * cutoff bands (quot = qmax*st near v = (qmax+1)*d - 0.5): soft fallback.
//  * pos 0 soft 4-term ascending sum when v < 1001: soft fallback.
// ---------------------------------------------------------------------------

static __device__ __forceinline__ unsigned long long evict_last_policy() {
    unsigned long long pol;
    asm("createpolicy.fractional.L2::evict_last.b64 %0, 1.0;" : "=l"(pol));
    return pol;
}
static __device__ __forceinline__ float ldg_el_f32(const float* p,
                                                   unsigned long long pol) {
    float v;
    asm volatile("ld.global.nc.L2::cache_hint.f32 %0, [%1], %2;"
                 : "=f"(v) : "l"(p), "l"(pol));
    return v;
}
static __device__ __forceinline__ int ldg_el_s32(const int* p,
                                                 unsigned long long pol) {
    int v;
    asm volatile("ld.global.nc.L2::cache_hint.b32 %0, [%1], %2;"
                 : "=r"(v) : "l"(p), "l"(pol));
    return v;
}

static __device__ __forceinline__ float sigm(float z) {
    return __fdividef(1.0f, 1.0f + __expf(-z));
}
// silu_threshold(x) = (silu(20x+10) - silu(20x-10)) / 20
static __device__ __forceinline__ float st_fast(float x) {
    float z1 = __fmaf_rn(20.0f, x, 10.0f);
    float z2 = __fmaf_rn(20.0f, x, -10.0f);
    return (z1 * sigm(z1) - z2 * sigm(z2)) * 0.05f;
}
// reference digit = floor(quot - floor(quot/10)*10); handles negative quot.
static __device__ __forceinline__ int mod10_digit(float quot) {
    return (int)floorf(quot - floorf(quot * 0.1f) * 10.0f);
}

// token for output column with offset j = col - op:
// digit token for j < n, newline for j == n, else 0.
static __device__ __forceinline__ float token_at(int j, int n, unsigned pk) {
    int pi = n - 1 - j;
    pi = pi < 0 ? 0 : (pi > 5 ? 5 : pi);
    float g = (float)((pk >> (pi * 4)) & 15u);
    return (j >= 0 && j < n) ? (48.0f + g) : ((j == n) ? 10.0f : 0.0f);
}

__global__ void __launch_bounds__(256)
c4_printf_2r_kernel(const float* __restrict__ mem,
                    const int*   __restrict__ addr,
                    const int*   __restrict__ outp,
                    float*       __restrict__ out,
                    int B, int M) {
    const unsigned FULL = 0xFFFFFFFFu;
    int lane = threadIdx.x & 31;
    int warp = (blockIdx.x * blockDim.x + threadIdx.x) >> 5;
    int base = warp * 2;                 // rows base, base+1
    if (base >= B) return;

    // --- owner phase: lanes 0..1 each own one row ------------------------------
    int  myrow = base + lane;
    bool owner = (lane < 2) && (myrow < B);

    float    v   = 0.0f;
    int      op  = 0;
    unsigned pkn = 0;                    // nibble digits | (n << 24)

    if (owner) {
        unsigned long long pol = evict_last_policy();
        int a = ldg_el_s32(addr + myrow, pol);
        op    = ldg_el_s32(outp + myrow, pol);
        // gather: keep the line resident in L2 across graph replays
        v     = fabsf(ldg_el_f32(mem + myrow * M + a, pol));

        // unsigned integer digit ladder (exact; v < 2^24)
        unsigned u  = (unsigned)v;
        unsigned q1 = u  / 10u;
        unsigned q2 = q1 / 10u;
        unsigned q3 = q2 / 10u;
        unsigned q4 = q3 / 10u;
        unsigned q5 = q4 / 10u;

        unsigned d1 = (q1 <= 101u) ? (q1 - 10u * q2) : 0u;
        unsigned d2 = (q2 <= 11u)  ? (q2 - 10u * q3) : 0u;
        unsigned d3 = (q3 <= 2u)   ? (q3 - 10u * q4) : 0u;
        unsigned d4 = (q4 <= 1u)   ? q4 : 0u;
        unsigned d5 = (q5 <= 1u)   ? q5 : 0u;

        int n = 1 + (q1 != 0u) + (q2 != 0u) + (q3 != 0u)
                  + (q4 != 0u) + (q5 != 0u);

        // qmax cutoff bands (~0.03% of rows)
        if (v > 1018.0f && v < 20001.0f) {
            if (fabsf(v - 1019.5f) < 1.41f) {
                float g = 1019.5f - v;
                float s = (g > -1.4011f) ? st_fast(g) : 0.0f;
                d1 = (unsigned)mod10_digit(101.0f * s);
            } else if (fabsf(v - 1199.5f) < 1.41f) {
                float g = 1199.5f - v;
                float s = (g > -1.4011f) ? st_fast(g) : 0.0f;
                d2 = (unsigned)mod10_digit(11.0f * s);
            } else if (fabsf(v - 2999.5f) < 1.41f) {
                float g = 2999.5f - v;
                float s = (g > -1.4011f) ? st_fast(g) : 0.0f;
                d3 = (unsigned)mod10_digit(2.0f * s);
            } else if (fabsf(v - 19999.5f) < 1.41f) {
                float g = 19999.5f - v;
                float s = (g > -1.4011f) ? st_fast(g) : 0.0f;
                d4 = (unsigned)mod10_digit(1.0f * s);
            }
        }

        // pos 0: soft 4-term ascending sum (per-lane serial; ~1% of rows)
        unsigned d0 = 0u;
        if (v < 1001.0f) {
            int qlo = (int)floorf(v - 1.93f) + 1;
            float quot = 0.0f;
            #pragma unroll
            for (int k = 0; k < 4; ++k) {
                int q = qlo + k;
                if (q >= 0 && q <= 999) {
                    float qf = (float)q;
                    float a1 = v - qf + 0.5f;        // lower gate arg (d = 1)
                    float a2 = qf + 0.5f - v;        // upper gate arg
                    quot += st_fast(a1) * st_fast(a2) * qf;
                }
            }
            d0 = (unsigned)mod10_digit(quot);
        }

        pkn = d0 | (d1 << 4) | (d2 << 8) | (d3 << 12)
            | (d4 << 16) | (d5 << 20) | ((unsigned)n << 24);
    }

    // --- epilogue: 2 rows, 2 coalesced 128B stores each --------------------------
    #pragma unroll
    for (int r = 0; r < 2; ++r) {
        int row = base + r;
        if (row >= B) break;
        unsigned pk = __shfl_sync(FULL, pkn, r);
        int      o  = __shfl_sync(FULL, op,  r);
        float    vv = __shfl_sync(FULL, v,   r);
        int nn = (int)(pk >> 24);

        // tokens occupy columns o..o+n (n <= 6): each 32-col half is live
        // only for a narrow op range — skip the dead half's select chain.
        float t0 = 0.0f, t1 = 0.0f;
        if (o <= 37)  t0 = token_at(lane - o, nn, pk);        // cols 0..31
        if (o >= 26)  t1 = token_at(lane + 32 - o, nn, pk);   // cols 32..63

        float* orow = out + row * 65;
        orow[lane]      = t0;
        orow[lane + 32] = t1;
        if (lane == 0) orow[64] = vv;    // appended value column (exact)
    }
}

extern "C" void kernel_launch(void* const* d_in, const int* in_sizes, int n_in,
                              void* d_out, int out_size) {
    const float* mem  = (const float*)d_in[0];   // [B, M] fp32
    const int*   addr = (const int*)d_in[1];     // [B] int32
    const int*   outp = (const int*)d_in[2];     // [B] int32
    float*       out  = (float*)d_out;           // [B, 65] fp32

    int B = in_sizes[1];
    int M = in_sizes[0] / B;

    // Best-measured shape (R11): 2 rows/warp, 8 warps/block -> 512 blocks.
    int rows_per_block = 16;
    int blocks = (B + rows_per_block - 1) / rows_per_block;
    c4_printf_2r_kernel<<<blocks, 256>>>(mem, addr, outp, out, B, M);
}

// round 15
// speedup vs baseline: 1.0047x; 1.0047x over previous
#include <cuda_runtime.h>

// ---------------------------------------------------------------------------
// R15 (FINAL): R11 verbatim — the best-measured configuration.
//   kernel 5.79us (ncu), dur 6.62us, rel_err 3.279e-6.
//
// Optimization history / floor evidence:
//   R3  warp-per-row, fill the chip        17.1 -> 11.0 us
//   R5  fast sigmoid replaces tanhf body   11.0 ->  8.7 us
//   R6  closed-form digits + rare fallback  8.7 ->  6.6 us
//   R10 integer ladder squeeze             kernel 6.4 -> 5.9 us
//   R11 2 rows/warp (halved inst count)    kernel 5.9 -> 5.8 us (floor)
//   Falsified: 8 rows/warp (R8), 64-thr blocks (R12), L2 evict_last pinning
//   (R14: DRAM gather traffic invariant across replays).
// Residual = launch/distribution overhead + one exposed DRAM gather chain,
// both invariant to kernel structure across R6-R14.
//
// Reference semantics (verified R2-R14, rel_err 3.279e-6):
//  * value = |mem[b, addr[b]]| exactly (eq_gate is an exact one-hot under
//    tanh saturation).
//  * floor(v/10^p) == unsigned /10 ladder on u = (unsigned)v  (v < 2^24).
//  * n = 1 + #{p in 1..5 : q_p != 0}.
//  * qmax clipping per pos {999,101,11,2,1,1} (reference loop break).
//  * cutoff bands (quot = qmax*st near v = (qmax+1)*d - 0.5): soft fallback.
//  * pos 0 soft 4-term ascending sum when v < 1001: soft fallback.
// ---------------------------------------------------------------------------

static __device__ __forceinline__ float sigm(float z) {
    return __fdividef(1.0f, 1.0f + __expf(-z));
}
// silu_threshold(x) = (silu(20x+10) - silu(20x-10)) / 20
static __device__ __forceinline__ float st_fast(float x) {
    float z1 = __fmaf_rn(20.0f, x, 10.0f);
    float z2 = __fmaf_rn(20.0f, x, -10.0f);
    return (z1 * sigm(z1) - z2 * sigm(z2)) * 0.05f;
}
// reference digit = floor(quot - floor(quot/10)*10); handles negative quot.
static __device__ __forceinline__ int mod10_digit(float quot) {
    return (int)floorf(quot - floorf(quot * 0.1f) * 10.0f);
}

// token for output column with offset j = col - op:
// digit token for j < n, newline for j == n, else 0.
static __device__ __forceinline__ float token_at(int j, int n, unsigned pk) {
    int pi = n - 1 - j;
    pi = pi < 0 ? 0 : (pi > 5 ? 5 : pi);
    float g = (float)((pk >> (pi * 4)) & 15u);
    return (j >= 0 && j < n) ? (48.0f + g) : ((j == n) ? 10.0f : 0.0f);
}

__global__ void __launch_bounds__(256)
c4_printf_2r_kernel(const float* __restrict__ mem,
                    const int*   __restrict__ addr,
                    const int*   __restrict__ outp,
                    float*       __restrict__ out,
                    int B, int M) {
    const unsigned FULL = 0xFFFFFFFFu;
    int lane = threadIdx.x & 31;
    int warp = (blockIdx.x * blockDim.x + threadIdx.x) >> 5;
    int base = warp * 2;                 // rows base, base+1
    if (base >= B) return;

    // --- owner phase: lanes 0..1 each own one row ------------------------------
    int  myrow = base + lane;
    bool owner = (lane < 2) && (myrow < B);

    float    v   = 0.0f;
    int      op  = 0;
    unsigned pkn = 0;                    // nibble digits | (n << 24)

    if (owner) {
        int a = __ldg(addr + myrow);
        op    = __ldg(outp + myrow);
        v     = fabsf(__ldg(mem + myrow * M + a));   // MLP=2 in one LDG

        // unsigned integer digit ladder (exact; v < 2^24)
        unsigned u  = (unsigned)v;
        unsigned q1 = u  / 10u;
        unsigned q2 = q1 / 10u;
        unsigned q3 = q2 / 10u;
        unsigned q4 = q3 / 10u;
        unsigned q5 = q4 / 10u;

        unsigned d1 = (q1 <= 101u) ? (q1 - 10u * q2) : 0u;
        unsigned d2 = (q2 <= 11u)  ? (q2 - 10u * q3) : 0u;
        unsigned d3 = (q3 <= 2u)   ? (q3 - 10u * q4) : 0u;
        unsigned d4 = (q4 <= 1u)   ? q4 : 0u;
        unsigned d5 = (q5 <= 1u)   ? q5 : 0u;

        int n = 1 + (q1 != 0u) + (q2 != 0u) + (q3 != 0u)
                  + (q4 != 0u) + (q5 != 0u);

        // qmax cutoff bands (~0.03% of rows)
        if (v > 1018.0f && v < 20001.0f) {
            if (fabsf(v - 1019.5f) < 1.41f) {
                float g = 1019.5f - v;
                float s = (g > -1.4011f) ? st_fast(g) : 0.0f;
                d1 = (unsigned)mod10_digit(101.0f * s);
            } else if (fabsf(v - 1199.5f) < 1.41f) {
                float g = 1199.5f - v;
                float s = (g > -1.4011f) ? st_fast(g) : 0.0f;
                d2 = (unsigned)mod10_digit(11.0f * s);
            } else if (fabsf(v - 2999.5f) < 1.41f) {
                float g = 2999.5f - v;
                float s = (g > -1.4011f) ? st_fast(g) : 0.0f;
                d3 = (unsigned)mod10_digit(2.0f * s);
            } else if (fabsf(v - 19999.5f) < 1.41f) {
                float g = 19999.5f - v;
                float s = (g > -1.4011f) ? st_fast(g) : 0.0f;
                d4 = (unsigned)mod10_digit(1.0f * s);
            }
        }

        // pos 0: soft 4-term ascending sum (per-lane serial; ~1% of rows)
        unsigned d0 = 0u;
        if (v < 1001.0f) {
            int qlo = (int)floorf(v - 1.93f) + 1;
            float quot = 0.0f;
            #pragma unroll
            for (int k = 0; k < 4; ++k) {
                int q = qlo + k;
                if (q >= 0 && q <= 999) {
                    float qf = (float)q;
                    float a1 = v - qf + 0.5f;        // lower gate arg (d = 1)
                    float a2 = qf + 0.5f - v;        // upper gate arg
                    quot += st_fast(a1) * st_fast(a2) * qf;
                }
            }
            d0 = (unsigned)mod10_digit(quot);
        }

        pkn = d0 | (d1 << 4) | (d2 << 8) | (d3 << 12)
            | (d4 << 16) | (d5 << 20) | ((unsigned)n << 24);
    }

    // --- epilogue: 2 rows, 2 coalesced 128B stores each --------------------------
    #pragma unroll
    for (int r = 0; r < 2; ++r) {
        int row = base + r;
        if (row >= B) break;
        unsigned pk = __shfl_sync(FULL, pkn, r);
        int      o  = __shfl_sync(FULL, op,  r);
        float    vv = __shfl_sync(FULL, v,   r);
        int nn = (int)(pk >> 24);

        // tokens occupy columns o..o+n (n <= 6): each 32-col half is live
        // only for a narrow op range — skip the dead half's select chain.
        float t0 = 0.0f, t1 = 0.0f;
        if (o <= 37)  t0 = token_at(lane - o, nn, pk);        // cols 0..31
        if (o >= 26)  t1 = token_at(lane + 32 - o, nn, pk);   // cols 32..63

        float* orow = out + row * 65;
        orow[lane]      = t0;
        orow[lane + 32] = t1;
        if (lane == 0) orow[64] = vv;    // appended value column (exact)
    }
}

extern "C" void kernel_launch(void* const* d_in, const int* in_sizes, int n_in,
                              void* d_out, int out_size) {
    const float* mem  = (const float*)d_in[0];   // [B, M] fp32
    const int*   addr = (const int*)d_in[1];     // [B] int32
    const int*   outp = (const int*)d_in[2];     // [B] int32
    float*       out  = (float*)d_out;           // [B, 65] fp32

    int B = in_sizes[1];
    int M = in_sizes[0] / B;

    // Best-measured shape (R11): 2 rows/warp, 8 warps/block -> 512 blocks.
    int rows_per_block = 16;
    int blocks = (B + rows_per_block - 1) / rows_per_block;
    c4_printf_2r_kernel<<<blocks, 256>>>(mem, addr, outp, out, B, M);
}

// round 16
// speedup vs baseline: 1.0385x; 1.0337x over previous
#include <cuda_runtime.h>

// ---------------------------------------------------------------------------
// R16 (FINAL): best-measured configuration (R11 body) + owner-lane value-
// column store (removes one shfl + predicate chain from the epilogue).
//
// Floor evidence (R6-R15): all variants since R6 land in a ~±0.25us noise
// band around kernel ~5.9us / dur ~6.7us. Residual = launch/distribution
// overhead at un-boosted clock + one exposed DRAM gather chain (L2
// evict_last pinning falsified in R14) + graph-replay overhead.
// Falsified levers: 8 rows/warp (R8), 64-thr blocks (R12), L2 pinning (R14).
// Win history: chip fill (R3, 17.1->11.0), fast sigmoid (R5, ->8.7),
// closed-form digits (R6, ->6.6), integer ladder (R10), 2 rows/warp (R11).
//
// Reference semantics (verified R2-R15, rel_err 3.279e-6):
//  * value = |mem[b, addr[b]]| exactly (eq_gate is an exact one-hot under
//    tanh saturation).
//  * floor(v/10^p) == unsigned /10 ladder on u = (unsigned)v  (v < 2^24).
//  * n = 1 + #{p in 1..5 : q_p != 0}.
//  * qmax clipping per pos {999,101,11,2,1,1} (reference loop break).
//  * cutoff bands (quot = qmax*st near v = (qmax+1)*d - 0.5): soft fallback.
//  * pos 0 soft 4-term ascending sum when v < 1001: soft fallback.
// ---------------------------------------------------------------------------

static __device__ __forceinline__ float sigm(float z) {
    return __fdividef(1.0f, 1.0f + __expf(-z));
}
// silu_threshold(x) = (silu(20x+10) - silu(20x-10)) / 20
static __device__ __forceinline__ float st_fast(float x) {
    float z1 = __fmaf_rn(20.0f, x, 10.0f);
    float z2 = __fmaf_rn(20.0f, x, -10.0f);
    return (z1 * sigm(z1) - z2 * sigm(z2)) * 0.05f;
}
// reference digit = floor(quot - floor(quot/10)*10); handles negative quot.
static __device__ __forceinline__ int mod10_digit(float quot) {
    return (int)floorf(quot - floorf(quot * 0.1f) * 10.0f);
}

// token for output column with offset j = col - op:
// digit token for j < n, newline for j == n, else 0.
static __device__ __forceinline__ float token_at(int j, int n, unsigned pk) {
    int pi = n - 1 - j;
    pi = pi < 0 ? 0 : (pi > 5 ? 5 : pi);
    float g = (float)((pk >> (pi * 4)) & 15u);
    return (j >= 0 && j < n) ? (48.0f + g) : ((j == n) ? 10.0f : 0.0f);
}

__global__ void __launch_bounds__(256)
c4_printf_2r_kernel(const float* __restrict__ mem,
                    const int*   __restrict__ addr,
                    const int*   __restrict__ outp,
                    float*       __restrict__ out,
                    int B, int M) {
    const unsigned FULL = 0xFFFFFFFFu;
    int lane = threadIdx.x & 31;
    int warp = (blockIdx.x * blockDim.x + threadIdx.x) >> 5;
    int base = warp * 2;                 // rows base, base+1
    if (base >= B) return;

    // --- owner phase: lanes 0..1 each own one row ------------------------------
    int  myrow = base + lane;
    bool owner = (lane < 2) && (myrow < B);

    float    v   = 0.0f;
    int      op  = 0;
    unsigned pkn = 0;                    // nibble digits | (n << 24)

    if (owner) {
        int a = __ldg(addr + myrow);
        op    = __ldg(outp + myrow);
        v     = fabsf(__ldg(mem + myrow * M + a));   // MLP=2 in one LDG

        // unsigned integer digit ladder (exact; v < 2^24)
        unsigned u  = (unsigned)v;
        unsigned q1 = u  / 10u;
        unsigned q2 = q1 / 10u;
        unsigned q3 = q2 / 10u;
        unsigned q4 = q3 / 10u;
        unsigned q5 = q4 / 10u;

        unsigned d1 = (q1 <= 101u) ? (q1 - 10u * q2) : 0u;
        unsigned d2 = (q2 <= 11u)  ? (q2 - 10u * q3) : 0u;
        unsigned d3 = (q3 <= 2u)   ? (q3 - 10u * q4) : 0u;
        unsigned d4 = (q4 <= 1u)   ? q4 : 0u;
        unsigned d5 = (q5 <= 1u)   ? q5 : 0u;

        int n = 1 + (q1 != 0u) + (q2 != 0u) + (q3 != 0u)
                  + (q4 != 0u) + (q5 != 0u);

        // qmax cutoff bands (~0.03% of rows)
        if (v > 1018.0f && v < 20001.0f) {
            if (fabsf(v - 1019.5f) < 1.41f) {
                float g = 1019.5f - v;
                float s = (g > -1.4011f) ? st_fast(g) : 0.0f;
                d1 = (unsigned)mod10_digit(101.0f * s);
            } else if (fabsf(v - 1199.5f) < 1.41f) {
                float g = 1199.5f - v;
                float s = (g > -1.4011f) ? st_fast(g) : 0.0f;
                d2 = (unsigned)mod10_digit(11.0f * s);
            } else if (fabsf(v - 2999.5f) < 1.41f) {
                float g = 2999.5f - v;
                float s = (g > -1.4011f) ? st_fast(g) : 0.0f;
                d3 = (unsigned)mod10_digit(2.0f * s);
            } else if (fabsf(v - 19999.5f) < 1.41f) {
                float g = 19999.5f - v;
                float s = (g > -1.4011f) ? st_fast(g) : 0.0f;
                d4 = (unsigned)mod10_digit(1.0f * s);
            }
        }

        // pos 0: soft 4-term ascending sum (per-lane serial; ~1% of rows)
        unsigned d0 = 0u;
        if (v < 1001.0f) {
            int qlo = (int)floorf(v - 1.93f) + 1;
            float quot = 0.0f;
            #pragma unroll
            for (int k = 0; k < 4; ++k) {
                int q = qlo + k;
                if (q >= 0 && q <= 999) {
                    float qf = (float)q;
                    float a1 = v - qf + 0.5f;        // lower gate arg (d = 1)
                    float a2 = qf + 0.5f - v;        // upper gate arg
                    quot += st_fast(a1) * st_fast(a2) * qf;
                }
            }
            d0 = (unsigned)mod10_digit(quot);
        }

        pkn = d0 | (d1 << 4) | (d2 << 8) | (d3 << 12)
            | (d4 << 16) | (d5 << 20) | ((unsigned)n << 24);

        // owner lane writes its own row's value column directly (exact);
        // removes the v shfl + lane==0 predicate from the epilogue loop.
        out[myrow * 65 + 64] = v;
    }

    // --- epilogue: 2 rows, 2 coalesced 128B stores each --------------------------
    #pragma unroll
    for (int r = 0; r < 2; ++r) {
        int row = base + r;
        if (row >= B) break;
        unsigned pk = __shfl_sync(FULL, pkn, r);
        int      o  = __shfl_sync(FULL, op,  r);
        int      nn = (int)((pk >> 24) & 7u);

        // tokens occupy columns o..o+n (n <= 6): each 32-col half is live
        // only for a narrow op range — skip the dead half's select chain.
        float t0 = 0.0f, t1 = 0.0f;
        if (o <= 37)  t0 = token_at(lane - o, nn, pk);        // cols 0..31
        if (o >= 26)  t1 = token_at(lane + 32 - o, nn, pk);   // cols 32..63

        float* orow = out + row * 65;
        orow[lane]      = t0;
        orow[lane + 32] = t1;
    }
}

extern "C" void kernel_launch(void* const* d_in, const int* in_sizes, int n_in,
                              void* d_out, int out_size) {
    const float* mem  = (const float*)d_in[0];   // [B, M] fp32
    const int*   addr = (const int*)d_in[1];     // [B] int32
    const int*   outp = (const int*)d_in[2];     // [B] int32
    float*       out  = (float*)d_out;           // [B, 65] fp32

    int B = in_sizes[1];
    int M = in_sizes[0] / B;

    // Best-measured shape (R11): 2 rows/warp, 8 warps/block -> 512 blocks.
    int rows_per_block = 16;
    int blocks = (B + rows_per_block - 1) / rows_per_block;
    c4_printf_2r_kernel<<<blocks, 256>>>(mem, addr, outp, out, B, M);
}